// round 16
// baseline (speedup 1.0000x reference)
#include <cuda_runtime.h>
#include <cuda_fp16.h>
#include <math.h>
#include <stdint.h>

#define Bn 2
#define Sn 2048
#define Dn 1024
#define Hn 16
#define HDn 64
#define BSn (Bn*Sn)      // 4096
#define N3D (3*Dn)       // 3072
#define NQKV (Bn*Hn*Sn*HDn)

// single-single wide stage (128m x 128n, k64): A 16KB | B 16KB = 32KB
#define SLOT_SS 32768
#define SMEM_SS (2*SLOT_SS)   // 65536
// scores single-shot (q split): Ah 16KB | Al 16KB | B 16KB
#define SMEM_SC 49152
// av single-single stage (128m x 64n, k64): A 16KB | B 8KB = 24KB
#define SLOT_AV 24576
#define SMEM_AV (2*SLOT_AV)   // 49152 -> 3 CTAs/SM

// ---------------- fp16 scratch (device globals) ----------------
__device__ __half s_hs_h[BSn*Dn];                    // hidden states single
__device__ __half s_wa_h[N3D*Dn];                    // w_attn^T single
__device__ __half s_wp_h[Dn*Dn];                     // w_proj^T single
__device__ __half g_q_h[NQKV], g_q_l[NQKV];          // q split   [bh][s][hd]
__device__ __half g_k_h[NQKV];                       // k single  [bh][s][hd]
__device__ __half g_v_h[NQKV];                       // v single  [bh][hd][s]
__device__ __half g_att_h[NQKV];                     // att single [bh][s][hd]
__device__ __half g_w_h[(size_t)Bn*Hn*Sn*Sn];        // weights single

// ---------------- helpers ----------------
__device__ __forceinline__ uint32_t s2u(const void* p) {
    return (uint32_t)__cvta_generic_to_shared(p);
}
__device__ __forceinline__ void ldsm4(uint32_t& r0, uint32_t& r1, uint32_t& r2,
                                      uint32_t& r3, uint32_t a) {
    asm volatile("ldmatrix.sync.aligned.m8n8.x4.shared.b16 {%0,%1,%2,%3},[%4];"
                 : "=r"(r0), "=r"(r1), "=r"(r2), "=r"(r3) : "r"(a));
}
#define MMAF(c, a, b) asm volatile( \
    "mma.sync.aligned.m16n8k16.row.col.f32.f16.f16.f32 " \
    "{%0,%1,%2,%3},{%4,%5,%6,%7},{%8,%9},{%0,%1,%2,%3};" \
    : "+f"((c)[0]), "+f"((c)[1]), "+f"((c)[2]), "+f"((c)[3]) \
    : "r"((a)[0]), "r"((a)[1]), "r"((a)[2]), "r"((a)[3]), "r"((b)[0]), "r"((b)[1]))

__device__ __forceinline__ void cpa16(uint32_t dst, const void* src) {
    asm volatile("cp.async.cg.shared.global [%0], [%1], 16;" :: "r"(dst), "l"(src));
}
#define CP_COMMIT() asm volatile("cp.async.commit_group;")
#define CP_WAIT0()  asm volatile("cp.async.wait_group 0;")

// byte offset of 16B chunk c (0..7) in swizzled 128B row
__device__ __forceinline__ uint32_t swz(int row, int c) {
    return (uint32_t)row * 128u + (uint32_t)((c ^ (row & 7)) << 4);
}

__device__ __forceinline__ void split2(float x, float y, uint32_t& ph, uint32_t& pl) {
    __half2 h2 = __floats2half2_rn(x, y);
    ph = *reinterpret_cast<uint32_t*>(&h2);
    __half2 l2 = __floats2half2_rn(x - __half2float(__low2half(h2)),
                                   y - __half2float(__high2half(h2)));
    pl = *reinterpret_cast<uint32_t*>(&l2);
}
__device__ __forceinline__ uint32_t pack2(float x, float y) {
    __half2 h2 = __floats2half2_rn(x, y);
    return *reinterpret_cast<uint32_t*>(&h2);
}

// single-single wide stage (k64): A @0 (128 rows), B @16384 (128 rows).
__device__ __forceinline__ void cstage_ss(uint32_t sb, float acc[4][4][4],
                                          int mbase, int nbase, int lane) {
    #pragma unroll
    for (int kk = 0; kk < 4; kk++) {
        uint32_t bf[4][2];
        #pragma unroll
        for (int jg = 0; jg < 2; jg++) {
            int brow = nbase + jg * 16 + (lane & 7) + ((lane >> 4) << 3);
            int bch = kk * 2 + ((lane >> 3) & 1);
            uint32_t r0, r1, r2, r3;
            ldsm4(r0, r1, r2, r3, sb + 16384u + swz(brow, bch));
            bf[jg * 2][0] = r0; bf[jg * 2][1] = r1;
            bf[jg * 2 + 1][0] = r2; bf[jg * 2 + 1][1] = r3;
        }
        #pragma unroll
        for (int i = 0; i < 4; i++) {
            int arow = mbase + i * 16 + (lane & 15);
            int ach = kk * 2 + (lane >> 4);
            uint32_t ah[4];
            ldsm4(ah[0], ah[1], ah[2], ah[3], sb + swz(arow, ach));
            #pragma unroll
            for (int j = 0; j < 4; j++) MMAF(acc[i][j], ah, bf[j]);
        }
    }
}

// scores stage (k64, single shot): split A (Ah @0, Al @16384), B @32768.
__device__ __forceinline__ void cstage_sc(uint32_t sb, float acc[4][4][4],
                                          int mbase, int nbase, int lane) {
    #pragma unroll
    for (int kk = 0; kk < 4; kk++) {
        uint32_t bf[4][2];
        #pragma unroll
        for (int jg = 0; jg < 2; jg++) {
            int brow = nbase + jg * 16 + (lane & 7) + ((lane >> 4) << 3);
            int bch = kk * 2 + ((lane >> 3) & 1);
            uint32_t r0, r1, r2, r3;
            ldsm4(r0, r1, r2, r3, sb + 32768u + swz(brow, bch));
            bf[jg * 2][0] = r0; bf[jg * 2][1] = r1;
            bf[jg * 2 + 1][0] = r2; bf[jg * 2 + 1][1] = r3;
        }
        #pragma unroll
        for (int i = 0; i < 4; i++) {
            int arow = mbase + i * 16 + (lane & 15);
            int ach = kk * 2 + (lane >> 4);
            uint32_t ah[4], al[4];
            ldsm4(ah[0], ah[1], ah[2], ah[3], sb + swz(arow, ach));
            ldsm4(al[0], al[1], al[2], al[3], sb + 16384u + swz(arow, ach));
            #pragma unroll
            for (int j = 0; j < 4; j++) {
                MMAF(acc[i][j], ah, bf[j]);
                MMAF(acc[i][j], al, bf[j]);
            }
        }
    }
}

// av stage (k64): A @0 (128 rows), B @16384 (64 rows). warp 32x32.
__device__ __forceinline__ void cstage_av(uint32_t sb, float acc[2][4][4],
                                          int mbase, int nbase, int lane) {
    #pragma unroll
    for (int kk = 0; kk < 4; kk++) {
        uint32_t bf[4][2];
        #pragma unroll
        for (int jg = 0; jg < 2; jg++) {
            int brow = nbase + jg * 16 + (lane & 7) + ((lane >> 4) << 3);
            int bch = kk * 2 + ((lane >> 3) & 1);
            uint32_t r0, r1, r2, r3;
            ldsm4(r0, r1, r2, r3, sb + 16384u + swz(brow, bch));
            bf[jg * 2][0] = r0; bf[jg * 2][1] = r1;
            bf[jg * 2 + 1][0] = r2; bf[jg * 2 + 1][1] = r3;
        }
        #pragma unroll
        for (int i = 0; i < 2; i++) {
            int arow = mbase + i * 16 + (lane & 15);
            int ach = kk * 2 + (lane >> 4);
            uint32_t ah[4];
            ldsm4(ah[0], ah[1], ah[2], ah[3], sb + swz(arow, ach));
            #pragma unroll
            for (int j = 0; j < 4; j++) MMAF(acc[i][j], ah, bf[j]);
        }
    }
}

// ---------------------------------------------------------------------------
// Kernel 0a: hidden states -> single fp16.
// ---------------------------------------------------------------------------
__global__ __launch_bounds__(256) void split_hs(const float* __restrict__ hs) {
    int i = (blockIdx.x * 256 + threadIdx.x) * 4;
    float4 v = *(const float4*)&hs[i];
    *(uint2*)&s_hs_h[i] = make_uint2(pack2(v.x, v.y), pack2(v.z, v.w));
}

// ---------------------------------------------------------------------------
// Kernel 0b: tiled transpose of [K,N] weight -> single fp16 [N,K].
// ---------------------------------------------------------------------------
__global__ __launch_bounds__(256) void split_transpose(const float* __restrict__ in,
                                                       __half* __restrict__ oh,
                                                       int K, int N) {
    __shared__ float t[32][33];
    int nb = blockIdx.x * 32, kb = blockIdx.y * 32;
    int tx = threadIdx.x & 31, ty = threadIdx.x >> 5;
    #pragma unroll
    for (int i = 0; i < 4; i++) {
        int r = ty + i * 8;
        t[r][tx] = in[(size_t)(kb + r) * N + nb + tx];
    }
    __syncthreads();
    #pragma unroll
    for (int i = 0; i < 4; i++) {
        int r = ty + i * 8;
        oh[(size_t)(nb + r) * K + kb + tx] = __float2half_rn(t[tx][r]);
    }
}

// ---------------------------------------------------------------------------
// Kernel 1: QKV projection (R13 pipeline, correct) + upper-tri zero prologue.
// 3840 zero blocks / 768 CTAs = 5 per CTA; stores retire under 16 tensor stages.
// ---------------------------------------------------------------------------
__global__ __launch_bounds__(256, 2) void qkv_gemm(const float* __restrict__ bias,
                                                   float* __restrict__ Wzero) {
    extern __shared__ __align__(16) char dynsmem[];
    const uint32_t smb = s2u(dynsmem);
    const int K = 1024;
    int tid = threadIdx.x, lane = tid & 31, wid = tid >> 5;
    int row0 = blockIdx.y * 128, col0 = blockIdx.x * 128;
    int mbase = (wid & 1) * 64, nbase = (wid >> 1) * 32;
    int srow = tid >> 1, sh = tid & 1;
    const __half* gA = s_hs_h + (size_t)(row0 + srow) * K + sh * 32;
    const __half* gB = s_wa_h + (size_t)(col0 + srow) * K + sh * 32;
    uint32_t dA[4];
    #pragma unroll
    for (int i = 0; i < 4; i++) dA[i] = swz(srow, sh * 4 + i);

    float acc[4][4][4] = {};
    const int T = K / 64;

    #define QISSUE(t) do { uint32_t sb = smb + ((t) & 1) * SLOT_SS; \
        _Pragma("unroll") for (int i = 0; i < 4; i++) { \
            cpa16(sb + dA[i],          gA + (t) * 64 + i * 8); \
            cpa16(sb + 16384 + dA[i],  gB + (t) * 64 + i * 8); } } while (0)

    QISSUE(0); CP_COMMIT();

    // ---- zero-fill prologue: 5 upper-tri 128x128 blocks per CTA ----
    {
        int cta = blockIdx.y * gridDim.x + blockIdx.x;   // 0..767
        float4 z = make_float4(0.f, 0.f, 0.f, 0.f);
        #pragma unroll
        for (int blk = 0; blk < 5; blk++) {
            int zb = cta * 5 + blk;            // 0..3839
            int bh = zb / 120;
            int t = zb - bh * 120;             // upper-tri pair index
            int qb = 0, cum = 0;
            #pragma unroll
            for (int q = 0; q < 15; q++) {
                int cnt = 15 - q;
                if (t < cum + cnt) { qb = q; break; }
                cum += cnt;
            }
            int kb = qb + 1 + (t - cum);
            float* base = Wzero + ((size_t)bh * Sn + qb * 128) * Sn + kb * 128;
            #pragma unroll
            for (int it = 0; it < 16; it++) {
                int e = tid + it * 256;        // 4096 float4s
                int r = e >> 5, c = (e & 31) * 4;
                *(float4*)&base[(size_t)r * Sn + c] = z;
            }
        }
    }

    for (int t = 0; t < T; t++) {
        CP_WAIT0();
        __syncthreads();
        if (t + 1 < T) QISSUE(t + 1);
        CP_COMMIT();
        cstage_ss(smb + (t & 1) * SLOT_SS, acc, mbase, nbase, lane);
    }
    #undef QISSUE

    #pragma unroll
    for (int i = 0; i < 4; i++) {
        #pragma unroll
        for (int j = 0; j < 4; j++) {
            int rr = row0 + mbase + i * 16 + (lane >> 2);
            int cc = col0 + nbase + j * 8 + (lane & 3) * 2;
            #pragma unroll
            for (int half = 0; half < 2; half++) {
                int r = rr + half * 8;
                int b = r >> 11, s = r & 2047;
                float v0 = acc[i][j][half * 2 + 0] + bias[cc];
                float v1 = acc[i][j][half * 2 + 1] + bias[cc + 1];
                int which = cc >> 10;
                int dcol = cc & 1023;
                int h = dcol >> 6, hd = dcol & 63;
                int bh = b * Hn + h;
                if (which == 0) {
                    uint32_t ph, pl; split2(v0, v1, ph, pl);
                    size_t idx = ((size_t)bh * Sn + s) * HDn + hd;
                    *(uint32_t*)&g_q_h[idx] = ph; *(uint32_t*)&g_q_l[idx] = pl;
                } else if (which == 1) {
                    size_t idx = ((size_t)bh * Sn + s) * HDn + hd;
                    *(uint32_t*)&g_k_h[idx] = pack2(v0, v1);
                } else {
                    uint32_t ph = pack2(v0, v1);
                    size_t i0 = ((size_t)bh * HDn + hd) * Sn + s;
                    size_t i1 = ((size_t)bh * HDn + hd + 1) * Sn + s;
                    ((uint16_t*)g_v_h)[i0] = (uint16_t)(ph & 0xffff);
                    ((uint16_t*)g_v_h)[i1] = (uint16_t)(ph >> 16);
                }
            }
        }
    }
}

// ---------------------------------------------------------------------------
// Kernel 2: raw scores, lower-tri 128q x 128k tiles, K=64 single-shot (R13).
// ---------------------------------------------------------------------------
__global__ __launch_bounds__(256, 2) void scores_kernel(const float* __restrict__ mask,
                                                        float* __restrict__ Wout) {
    extern __shared__ __align__(16) char dynsmem[];
    const uint32_t smb = s2u(dynsmem);
    int idx = blockIdx.x;
    int qb = (int)((sqrtf(8.0f * idx + 1.0f) - 1.0f) * 0.5f);
    while ((qb + 1) * (qb + 2) / 2 <= idx) qb++;
    while (qb * (qb + 1) / 2 > idx) qb--;
    int kb = idx - qb * (qb + 1) / 2;
    int bh = blockIdx.y;
    int bb = bh >> 4;
    int tid = threadIdx.x, lane = tid & 31, wid = tid >> 5;
    int row0 = qb * 128, col0 = kb * 128;
    int mbase = (wid & 1) * 64, nbase = (wid >> 1) * 32;
    int srow = tid >> 1, sh = tid & 1;
    const __half* gAh = g_q_h + ((size_t)bh * Sn + row0 + srow) * HDn + sh * 32;
    const __half* gAl = g_q_l + ((size_t)bh * Sn + row0 + srow) * HDn + sh * 32;
    const __half* gB  = g_k_h + ((size_t)bh * Sn + col0 + srow) * HDn + sh * 32;

    #pragma unroll
    for (int i = 0; i < 4; i++) {
        uint32_t d = swz(srow, sh * 4 + i);
        cpa16(smb + d,          gAh + i * 8);
        cpa16(smb + 16384 + d,  gAl + i * 8);
        cpa16(smb + 32768 + d,  gB  + i * 8);
    }
    CP_COMMIT();
    CP_WAIT0();
    __syncthreads();

    float acc[4][4][4] = {};
    cstage_sc(smb, acc, mbase, nbase, lane);

    const float scale = 0.125f;
    #pragma unroll
    for (int i = 0; i < 4; i++) {
        #pragma unroll
        for (int j = 0; j < 4; j++) {
            int rr = row0 + mbase + i * 16 + (lane >> 2);
            int cc = col0 + nbase + j * 8 + (lane & 3) * 2;
            #pragma unroll
            for (int half = 0; half < 2; half++) {
                int r = rr + half * 8;
                float* orow = Wout + ((size_t)bh * Sn + r) * Sn;
                orow[cc]     = acc[i][j][half * 2 + 0] * scale + mask[bb * Sn + cc];
                orow[cc + 1] = acc[i][j][half * 2 + 1] * scale + mask[bb * Sn + cc + 1];
            }
        }
    }
}

// ---------------------------------------------------------------------------
// Kernel 3: row softmax over the causal band only (tail pre-zeroed by qkv).
// ---------------------------------------------------------------------------
__global__ __launch_bounds__(256) void softmax_kernel(float* __restrict__ Wm) {
    __shared__ float buf[Sn];
    __shared__ float red[8];
    int row = blockIdx.x;
    int q = row & (Sn - 1);
    int len = q + 1;
    int blockend = ((q >> 7) + 1) << 7;
    float* wrow = Wm + (size_t)row * Sn;
    size_t wb = (size_t)row * Sn;
    int tid = threadIdx.x;
    int lane = tid & 31, warp = tid >> 5;

    float mx = -1e30f;
    for (int c = tid * 4; c < blockend; c += 1024) {
        float4 v = *(const float4*)&wrow[c];
        *(float4*)&buf[c] = v;
        if (c + 3 < len) {
            mx = fmaxf(mx, fmaxf(fmaxf(v.x, v.y), fmaxf(v.z, v.w)));
        } else {
            if (c     < len) mx = fmaxf(mx, v.x);
            if (c + 1 < len) mx = fmaxf(mx, v.y);
            if (c + 2 < len) mx = fmaxf(mx, v.z);
            if (c + 3 < len) mx = fmaxf(mx, v.w);
        }
    }
    #pragma unroll
    for (int o = 16; o > 0; o >>= 1) mx = fmaxf(mx, __shfl_xor_sync(0xffffffffu, mx, o));
    if (lane == 0) red[warp] = mx;
    __syncthreads();
    if (tid < 32) {
        float t = (tid < 8) ? red[tid] : -1e30f;
        #pragma unroll
        for (int o = 4; o > 0; o >>= 1) t = fmaxf(t, __shfl_xor_sync(0xffffffffu, t, o));
        if (tid == 0) red[0] = t;
    }
    __syncthreads();
    mx = red[0];
    __syncthreads();

    float sum = 0.0f;
    for (int c = tid * 4; c < blockend; c += 1024) {
        float4 v = *(const float4*)&buf[c];
        float e0 = (c     < len) ? __expf(v.x - mx) : 0.0f;
        float e1 = (c + 1 < len) ? __expf(v.y - mx) : 0.0f;
        float e2 = (c + 2 < len) ? __expf(v.z - mx) : 0.0f;
        float e3 = (c + 3 < len) ? __expf(v.w - mx) : 0.0f;
        sum += (e0 + e1) + (e2 + e3);
        *(float4*)&buf[c] = make_float4(e0, e1, e2, e3);
    }
    #pragma unroll
    for (int o = 16; o > 0; o >>= 1) sum += __shfl_xor_sync(0xffffffffu, sum, o);
    if (lane == 0) red[warp] = sum;
    __syncthreads();
    if (tid < 32) {
        float t = (tid < 8) ? red[tid] : 0.0f;
        #pragma unroll
        for (int o = 4; o > 0; o >>= 1) t += __shfl_xor_sync(0xffffffffu, t, o);
        if (tid == 0) red[0] = t;
    }
    __syncthreads();
    float inv = 1.0f / red[0];

    for (int c = tid * 4; c < blockend; c += 1024) {
        float4 v = *(const float4*)&buf[c];
        v.x *= inv; v.y *= inv; v.z *= inv; v.w *= inv;
        *(float4*)&wrow[c] = v;
        *(uint2*)&g_w_h[wb + c] = make_uint2(pack2(v.x, v.y), pack2(v.z, v.w));
    }
}

// ---------------------------------------------------------------------------
// Kernel 4: attn_heads = weights @ V (unchanged from R13).
// ---------------------------------------------------------------------------
__global__ __launch_bounds__(256, 3) void av_kernel() {
    extern __shared__ __align__(16) char dynsmem[];
    const uint32_t smb = s2u(dynsmem);
    int qb = gridDim.x - 1 - blockIdx.x;
    int bh = blockIdx.y;
    int tid = threadIdx.x, lane = tid & 31, wid = tid >> 5;
    int row0 = qb * 128;
    int mbase = (wid & 3) * 32, nbase = (wid >> 2) * 32;
    int srow = tid >> 1, sh = tid & 1;
    int brow = tid >> 2, bq = tid & 3;
    const __half* gA = g_w_h + (size_t)bh * Sn * Sn + (size_t)(row0 + srow) * Sn + sh * 32;
    const __half* gB = g_v_h + ((size_t)bh * HDn + brow) * Sn + bq * 16;
    uint32_t dA[4];
    #pragma unroll
    for (int i = 0; i < 4; i++) dA[i] = swz(srow, sh * 4 + i);
    uint32_t dB0 = 16384u + swz(brow, bq * 2), dB1 = 16384u + swz(brow, bq * 2 + 1);

    float acc[2][4][4] = {};
    const int T = (qb + 1) * 2;

    #define AISSUE(t) do { uint32_t sb = smb + ((t) & 1) * SLOT_AV; \
        _Pragma("unroll") for (int i = 0; i < 4; i++) \
            cpa16(sb + dA[i], gA + (t) * 64 + i * 8); \
        cpa16(sb + dB0, gB + (t) * 64);  cpa16(sb + dB1, gB + (t) * 64 + 8); } while (0)

    AISSUE(0); CP_COMMIT();
    for (int t = 0; t < T; t++) {
        CP_WAIT0();
        __syncthreads();
        if (t + 1 < T) AISSUE(t + 1);
        CP_COMMIT();
        cstage_av(smb + (t & 1) * SLOT_AV, acc, mbase, nbase, lane);
    }
    #undef AISSUE

    #pragma unroll
    for (int i = 0; i < 2; i++) {
        #pragma unroll
        for (int j = 0; j < 4; j++) {
            int rr = row0 + mbase + i * 16 + (lane >> 2);
            int cc = nbase + j * 8 + (lane & 3) * 2;
            #pragma unroll
            for (int half = 0; half < 2; half++) {
                int r = rr + half * 8;
                size_t idx = ((size_t)bh * Sn + r) * HDn + cc;
                *(uint32_t*)&g_att_h[idx] =
                    pack2(acc[i][j][half * 2 + 0], acc[i][j][half * 2 + 1]);
            }
        }
    }
}

// ---------------------------------------------------------------------------
// Kernel 5: output projection (unchanged from R13).
// ---------------------------------------------------------------------------
__global__ __launch_bounds__(256, 2) void proj_gemm(const float* __restrict__ bias,
                                                    float* __restrict__ out) {
    extern __shared__ __align__(16) char dynsmem[];
    const uint32_t smb = s2u(dynsmem);
    const int K = 1024, N = 1024;
    int tid = threadIdx.x, lane = tid & 31, wid = tid >> 5;
    int row0 = blockIdx.y * 128, col0 = blockIdx.x * 128;
    int mbase = (wid & 1) * 64, nbase = (wid >> 1) * 32;
    int srow = tid >> 1, sh = tid & 1;
    int arow = row0 + srow;
    int ab = arow >> 11, as = arow & 2047;
    size_t abase = (((size_t)ab * Hn) * Sn + as) * HDn + sh * 32;
    const __half* gB = s_wp_h + (size_t)(col0 + srow) * K + sh * 32;
    uint32_t dA[4];
    #pragma unroll
    for (int i = 0; i < 4; i++) dA[i] = swz(srow, sh * 4 + i);

    float acc[4][4][4] = {};
    const int T = K / 64;

    #define PISSUE(t) do { uint32_t sb = smb + ((t) & 1) * SLOT_SS; \
        size_t so = abase + (size_t)(t) * Sn * HDn; \
        _Pragma("unroll") for (int i = 0; i < 4; i++) { \
            cpa16(sb + dA[i],          g_att_h + so + i * 8); \
            cpa16(sb + 16384 + dA[i],  gB + (t) * 64 + i * 8); } } while (0)

    PISSUE(0); CP_COMMIT();
    for (int t = 0; t < T; t++) {
        CP_WAIT0();
        __syncthreads();
        if (t + 1 < T) PISSUE(t + 1);
        CP_COMMIT();
        cstage_ss(smb + (t & 1) * SLOT_SS, acc, mbase, nbase, lane);
    }
    #undef PISSUE

    #pragma unroll
    for (int i = 0; i < 4; i++) {
        #pragma unroll
        for (int j = 0; j < 4; j++) {
            int rr = row0 + mbase + i * 16 + (lane >> 2);
            int cc = col0 + nbase + j * 8 + (lane & 3) * 2;
            #pragma unroll
            for (int half = 0; half < 2; half++) {
                int r = rr + half * 8;
                out[(size_t)r * N + cc]     = acc[i][j][half * 2 + 0] + bias[cc];
                out[(size_t)r * N + cc + 1] = acc[i][j][half * 2 + 1] + bias[cc + 1];
            }
        }
    }
}

// ---------------------------------------------------------------------------
extern "C" void kernel_launch(void* const* d_in, const int* in_sizes, int n_in,
                              void* d_out, int out_size) {
    (void)in_sizes; (void)n_in; (void)out_size;
    const float* hs     = (const float*)d_in[0];
    const float* mask   = (const float*)d_in[1];
    const float* w_attn = (const float*)d_in[2];
    const float* b_attn = (const float*)d_in[3];
    const float* w_proj = (const float*)d_in[4];
    const float* b_proj = (const float*)d_in[5];

    float* attn_out = (float*)d_out;                          // [B,S,D]
    float* weights  = (float*)d_out + (size_t)Bn * Sn * Dn;   // [B,H,S,S]

    cudaFuncSetAttribute(qkv_gemm,      cudaFuncAttributeMaxDynamicSharedMemorySize, SMEM_SS);
    cudaFuncSetAttribute(scores_kernel, cudaFuncAttributeMaxDynamicSharedMemorySize, SMEM_SC);
    cudaFuncSetAttribute(av_kernel,     cudaFuncAttributeMaxDynamicSharedMemorySize, SMEM_AV);
    cudaFuncSetAttribute(proj_gemm,     cudaFuncAttributeMaxDynamicSharedMemorySize, SMEM_SS);

    __half *wa_h, *wp_h;
    cudaGetSymbolAddress((void**)&wa_h, s_wa_h);
    cudaGetSymbolAddress((void**)&wp_h, s_wp_h);

    split_hs<<<BSn * Dn / 1024, 256>>>(hs);
    split_transpose<<<dim3(N3D / 32, Dn / 32), 256>>>(w_attn, wa_h, Dn, N3D);
    split_transpose<<<dim3(Dn / 32, Dn / 32), 256>>>(w_proj, wp_h, Dn, Dn);
    qkv_gemm<<<dim3(N3D / 128, BSn / 128), 256, SMEM_SS>>>(b_attn, weights);
    scores_kernel<<<dim3(136, Bn * Hn), 256, SMEM_SC>>>(mask, weights);
    softmax_kernel<<<dim3(Bn * Hn * Sn), 256>>>(weights);
    av_kernel<<<dim3(Sn / 128, Bn * Hn), 256, SMEM_AV>>>();
    proj_gemm<<<dim3(Dn / 128, BSn / 128), 256, SMEM_SS>>>(b_proj, attn_out);
}

// round 17
// speedup vs baseline: 1.0185x; 1.0185x over previous
#include <cuda_runtime.h>
#include <cuda_fp16.h>
#include <math.h>
#include <stdint.h>

#define Bn 2
#define Sn 2048
#define Dn 1024
#define Hn 16
#define HDn 64
#define BSn (Bn*Sn)      // 4096
#define N3D (3*Dn)       // 3072
#define NQKV (Bn*Hn*Sn*HDn)

// single-single wide stage (128m x 128n, k64): A 16KB | B 16KB = 32KB
#define SLOT_SS 32768
#define SMEM_SS (2*SLOT_SS)   // 65536
// scores single-shot (q split): Ah 16KB | Al 16KB | B 16KB
#define SMEM_SC 49152
// av single-single stage (128m x 64n, k64): A 16KB | B 8KB = 24KB
#define SLOT_AV 24576
#define SMEM_AV (2*SLOT_AV)   // 49152 -> 3 CTAs/SM

// ---------------- fp16 scratch (device globals) ----------------
__device__ __half s_hs_h[BSn*Dn];                    // hidden states single
__device__ __half s_wa_h[N3D*Dn];                    // w_attn^T single
__device__ __half s_wp_h[Dn*Dn];                     // w_proj^T single
__device__ __half g_q_h[NQKV], g_q_l[NQKV];          // q split   [bh][s][hd]
__device__ __half g_k_h[NQKV];                       // k single  [bh][s][hd]
__device__ __half g_v_h[NQKV];                       // v single  [bh][hd][s]
__device__ __half g_att_h[NQKV];                     // att single [bh][s][hd]
__device__ __half g_w_h[(size_t)Bn*Hn*Sn*Sn];        // weights single

// ---------------- helpers ----------------
__device__ __forceinline__ uint32_t s2u(const void* p) {
    return (uint32_t)__cvta_generic_to_shared(p);
}
__device__ __forceinline__ void ldsm4(uint32_t& r0, uint32_t& r1, uint32_t& r2,
                                      uint32_t& r3, uint32_t a) {
    asm volatile("ldmatrix.sync.aligned.m8n8.x4.shared.b16 {%0,%1,%2,%3},[%4];"
                 : "=r"(r0), "=r"(r1), "=r"(r2), "=r"(r3) : "r"(a));
}
#define MMAF(c, a, b) asm volatile( \
    "mma.sync.aligned.m16n8k16.row.col.f32.f16.f16.f32 " \
    "{%0,%1,%2,%3},{%4,%5,%6,%7},{%8,%9},{%0,%1,%2,%3};" \
    : "+f"((c)[0]), "+f"((c)[1]), "+f"((c)[2]), "+f"((c)[3]) \
    : "r"((a)[0]), "r"((a)[1]), "r"((a)[2]), "r"((a)[3]), "r"((b)[0]), "r"((b)[1]))

__device__ __forceinline__ void cpa16(uint32_t dst, const void* src) {
    asm volatile("cp.async.cg.shared.global [%0], [%1], 16;" :: "r"(dst), "l"(src));
}
#define CP_COMMIT() asm volatile("cp.async.commit_group;")
#define CP_WAIT0()  asm volatile("cp.async.wait_group 0;")

// byte offset of 16B chunk c (0..7) in swizzled 128B row
__device__ __forceinline__ uint32_t swz(int row, int c) {
    return (uint32_t)row * 128u + (uint32_t)((c ^ (row & 7)) << 4);
}

__device__ __forceinline__ void split2(float x, float y, uint32_t& ph, uint32_t& pl) {
    __half2 h2 = __floats2half2_rn(x, y);
    ph = *reinterpret_cast<uint32_t*>(&h2);
    __half2 l2 = __floats2half2_rn(x - __half2float(__low2half(h2)),
                                   y - __half2float(__high2half(h2)));
    pl = *reinterpret_cast<uint32_t*>(&l2);
}
__device__ __forceinline__ uint32_t pack2(float x, float y) {
    __half2 h2 = __floats2half2_rn(x, y);
    return *reinterpret_cast<uint32_t*>(&h2);
}

// single-single wide stage (k64): A @0 (128 rows), B @16384 (128 rows).
__device__ __forceinline__ void cstage_ss(uint32_t sb, float acc[4][4][4],
                                          int mbase, int nbase, int lane) {
    #pragma unroll
    for (int kk = 0; kk < 4; kk++) {
        uint32_t bf[4][2];
        #pragma unroll
        for (int jg = 0; jg < 2; jg++) {
            int brow = nbase + jg * 16 + (lane & 7) + ((lane >> 4) << 3);
            int bch = kk * 2 + ((lane >> 3) & 1);
            uint32_t r0, r1, r2, r3;
            ldsm4(r0, r1, r2, r3, sb + 16384u + swz(brow, bch));
            bf[jg * 2][0] = r0; bf[jg * 2][1] = r1;
            bf[jg * 2 + 1][0] = r2; bf[jg * 2 + 1][1] = r3;
        }
        #pragma unroll
        for (int i = 0; i < 4; i++) {
            int arow = mbase + i * 16 + (lane & 15);
            int ach = kk * 2 + (lane >> 4);
            uint32_t ah[4];
            ldsm4(ah[0], ah[1], ah[2], ah[3], sb + swz(arow, ach));
            #pragma unroll
            for (int j = 0; j < 4; j++) MMAF(acc[i][j], ah, bf[j]);
        }
    }
}

// scores stage (k64, single shot): split A (Ah @0, Al @16384), B @32768.
__device__ __forceinline__ void cstage_sc(uint32_t sb, float acc[4][4][4],
                                          int mbase, int nbase, int lane) {
    #pragma unroll
    for (int kk = 0; kk < 4; kk++) {
        uint32_t bf[4][2];
        #pragma unroll
        for (int jg = 0; jg < 2; jg++) {
            int brow = nbase + jg * 16 + (lane & 7) + ((lane >> 4) << 3);
            int bch = kk * 2 + ((lane >> 3) & 1);
            uint32_t r0, r1, r2, r3;
            ldsm4(r0, r1, r2, r3, sb + 32768u + swz(brow, bch));
            bf[jg * 2][0] = r0; bf[jg * 2][1] = r1;
            bf[jg * 2 + 1][0] = r2; bf[jg * 2 + 1][1] = r3;
        }
        #pragma unroll
        for (int i = 0; i < 4; i++) {
            int arow = mbase + i * 16 + (lane & 15);
            int ach = kk * 2 + (lane >> 4);
            uint32_t ah[4], al[4];
            ldsm4(ah[0], ah[1], ah[2], ah[3], sb + swz(arow, ach));
            ldsm4(al[0], al[1], al[2], al[3], sb + 16384u + swz(arow, ach));
            #pragma unroll
            for (int j = 0; j < 4; j++) {
                MMAF(acc[i][j], ah, bf[j]);
                MMAF(acc[i][j], al, bf[j]);
            }
        }
    }
}

// av stage (k64): A @0 (128 rows), B @16384 (64 rows). warp 32x32.
__device__ __forceinline__ void cstage_av(uint32_t sb, float acc[2][4][4],
                                          int mbase, int nbase, int lane) {
    #pragma unroll
    for (int kk = 0; kk < 4; kk++) {
        uint32_t bf[4][2];
        #pragma unroll
        for (int jg = 0; jg < 2; jg++) {
            int brow = nbase + jg * 16 + (lane & 7) + ((lane >> 4) << 3);
            int bch = kk * 2 + ((lane >> 3) & 1);
            uint32_t r0, r1, r2, r3;
            ldsm4(r0, r1, r2, r3, sb + 16384u + swz(brow, bch));
            bf[jg * 2][0] = r0; bf[jg * 2][1] = r1;
            bf[jg * 2 + 1][0] = r2; bf[jg * 2 + 1][1] = r3;
        }
        #pragma unroll
        for (int i = 0; i < 2; i++) {
            int arow = mbase + i * 16 + (lane & 15);
            int ach = kk * 2 + (lane >> 4);
            uint32_t ah[4];
            ldsm4(ah[0], ah[1], ah[2], ah[3], sb + swz(arow, ach));
            #pragma unroll
            for (int j = 0; j < 4; j++) MMAF(acc[i][j], ah, bf[j]);
        }
    }
}

// ---------------------------------------------------------------------------
// Kernel 0a: hidden states -> single fp16.
// ---------------------------------------------------------------------------
__global__ __launch_bounds__(256) void split_hs(const float* __restrict__ hs) {
    int i = (blockIdx.x * 256 + threadIdx.x) * 4;
    float4 v = *(const float4*)&hs[i];
    *(uint2*)&s_hs_h[i] = make_uint2(pack2(v.x, v.y), pack2(v.z, v.w));
}

// ---------------------------------------------------------------------------
// Kernel 0b: tiled transpose of [K,N] weight -> single fp16 [N,K].
// ---------------------------------------------------------------------------
__global__ __launch_bounds__(256) void split_transpose(const float* __restrict__ in,
                                                       __half* __restrict__ oh,
                                                       int K, int N) {
    __shared__ float t[32][33];
    int nb = blockIdx.x * 32, kb = blockIdx.y * 32;
    int tx = threadIdx.x & 31, ty = threadIdx.x >> 5;
    #pragma unroll
    for (int i = 0; i < 4; i++) {
        int r = ty + i * 8;
        t[r][tx] = in[(size_t)(kb + r) * N + nb + tx];
    }
    __syncthreads();
    #pragma unroll
    for (int i = 0; i < 4; i++) {
        int r = ty + i * 8;
        oh[(size_t)(nb + r) * K + kb + tx] = __float2half_rn(t[tx][r]);
    }
}

// ---------------------------------------------------------------------------
// Kernel 1: QKV projection (R13 pipeline) + INTERLEAVED upper-tri zero stores:
// 5 float4 STG per thread per mainloop stage (16 stages x 5 blocks), issued
// between the cp.async issue and the MMA batch so they drain under tensor time.
// ---------------------------------------------------------------------------
__global__ __launch_bounds__(256, 2) void qkv_gemm(const float* __restrict__ bias,
                                                   float* __restrict__ Wzero) {
    extern __shared__ __align__(16) char dynsmem[];
    const uint32_t smb = s2u(dynsmem);
    const int K = 1024;
    int tid = threadIdx.x, lane = tid & 31, wid = tid >> 5;
    int row0 = blockIdx.y * 128, col0 = blockIdx.x * 128;
    int mbase = (wid & 1) * 64, nbase = (wid >> 1) * 32;
    int srow = tid >> 1, sh = tid & 1;
    const __half* gA = s_hs_h + (size_t)(row0 + srow) * K + sh * 32;
    const __half* gB = s_wa_h + (size_t)(col0 + srow) * K + sh * 32;
    uint32_t dA[4];
    #pragma unroll
    for (int i = 0; i < 4; i++) dA[i] = swz(srow, sh * 4 + i);

    // precompute 5 zero-block base pointers (upper-tri blocks of weights)
    float* zbase[5];
    {
        int cta = blockIdx.y * gridDim.x + blockIdx.x;   // 0..767
        #pragma unroll
        for (int blk = 0; blk < 5; blk++) {
            int zb = cta * 5 + blk;            // 0..3839
            int bh = zb / 120;
            int t = zb - bh * 120;
            int qb = 0, cum = 0;
            #pragma unroll
            for (int q = 0; q < 15; q++) {
                int cnt = 15 - q;
                if (t < cum + cnt) { qb = q; break; }
                cum += cnt;
            }
            int kb = qb + 1 + (t - cum);
            zbase[blk] = Wzero + ((size_t)bh * Sn + qb * 128) * Sn + kb * 128;
        }
    }
    const float4 zv = make_float4(0.f, 0.f, 0.f, 0.f);

    float acc[4][4][4] = {};
    const int T = K / 64;   // 16 stages

    #define QISSUE(t) do { uint32_t sb = smb + ((t) & 1) * SLOT_SS; \
        _Pragma("unroll") for (int i = 0; i < 4; i++) { \
            cpa16(sb + dA[i],          gA + (t) * 64 + i * 8); \
            cpa16(sb + 16384 + dA[i],  gB + (t) * 64 + i * 8); } } while (0)

    QISSUE(0); CP_COMMIT();
    for (int t = 0; t < T; t++) {
        CP_WAIT0();
        __syncthreads();
        if (t + 1 < T) QISSUE(t + 1);
        CP_COMMIT();
        // interleaved zero stores: slice t of each of the 5 blocks
        {
            int e = tid + t * 256;            // 0..4095 over 16 stages
            int r = e >> 5, c = (e & 31) * 4;
            size_t off = (size_t)r * Sn + c;
            #pragma unroll
            for (int blk = 0; blk < 5; blk++)
                *(float4*)&zbase[blk][off] = zv;
        }
        cstage_ss(smb + (t & 1) * SLOT_SS, acc, mbase, nbase, lane);
    }
    #undef QISSUE

    #pragma unroll
    for (int i = 0; i < 4; i++) {
        #pragma unroll
        for (int j = 0; j < 4; j++) {
            int rr = row0 + mbase + i * 16 + (lane >> 2);
            int cc = col0 + nbase + j * 8 + (lane & 3) * 2;
            #pragma unroll
            for (int half = 0; half < 2; half++) {
                int r = rr + half * 8;
                int b = r >> 11, s = r & 2047;
                float v0 = acc[i][j][half * 2 + 0] + bias[cc];
                float v1 = acc[i][j][half * 2 + 1] + bias[cc + 1];
                int which = cc >> 10;
                int dcol = cc & 1023;
                int h = dcol >> 6, hd = dcol & 63;
                int bh = b * Hn + h;
                if (which == 0) {
                    uint32_t ph, pl; split2(v0, v1, ph, pl);
                    size_t idx = ((size_t)bh * Sn + s) * HDn + hd;
                    *(uint32_t*)&g_q_h[idx] = ph; *(uint32_t*)&g_q_l[idx] = pl;
                } else if (which == 1) {
                    size_t idx = ((size_t)bh * Sn + s) * HDn + hd;
                    *(uint32_t*)&g_k_h[idx] = pack2(v0, v1);
                } else {
                    uint32_t ph = pack2(v0, v1);
                    size_t i0 = ((size_t)bh * HDn + hd) * Sn + s;
                    size_t i1 = ((size_t)bh * HDn + hd + 1) * Sn + s;
                    ((uint16_t*)g_v_h)[i0] = (uint16_t)(ph & 0xffff);
                    ((uint16_t*)g_v_h)[i1] = (uint16_t)(ph >> 16);
                }
            }
        }
    }
}

// ---------------------------------------------------------------------------
// Kernel 2: raw scores, lower-tri 128q x 128k tiles, K=64 single-shot (R13).
// ---------------------------------------------------------------------------
__global__ __launch_bounds__(256, 2) void scores_kernel(const float* __restrict__ mask,
                                                        float* __restrict__ Wout) {
    extern __shared__ __align__(16) char dynsmem[];
    const uint32_t smb = s2u(dynsmem);
    int idx = blockIdx.x;
    int qb = (int)((sqrtf(8.0f * idx + 1.0f) - 1.0f) * 0.5f);
    while ((qb + 1) * (qb + 2) / 2 <= idx) qb++;
    while (qb * (qb + 1) / 2 > idx) qb--;
    int kb = idx - qb * (qb + 1) / 2;
    int bh = blockIdx.y;
    int bb = bh >> 4;
    int tid = threadIdx.x, lane = tid & 31, wid = tid >> 5;
    int row0 = qb * 128, col0 = kb * 128;
    int mbase = (wid & 1) * 64, nbase = (wid >> 1) * 32;
    int srow = tid >> 1, sh = tid & 1;
    const __half* gAh = g_q_h + ((size_t)bh * Sn + row0 + srow) * HDn + sh * 32;
    const __half* gAl = g_q_l + ((size_t)bh * Sn + row0 + srow) * HDn + sh * 32;
    const __half* gB  = g_k_h + ((size_t)bh * Sn + col0 + srow) * HDn + sh * 32;

    #pragma unroll
    for (int i = 0; i < 4; i++) {
        uint32_t d = swz(srow, sh * 4 + i);
        cpa16(smb + d,          gAh + i * 8);
        cpa16(smb + 16384 + d,  gAl + i * 8);
        cpa16(smb + 32768 + d,  gB  + i * 8);
    }
    CP_COMMIT();
    CP_WAIT0();
    __syncthreads();

    float acc[4][4][4] = {};
    cstage_sc(smb, acc, mbase, nbase, lane);

    const float scale = 0.125f;
    #pragma unroll
    for (int i = 0; i < 4; i++) {
        #pragma unroll
        for (int j = 0; j < 4; j++) {
            int rr = row0 + mbase + i * 16 + (lane >> 2);
            int cc = col0 + nbase + j * 8 + (lane & 3) * 2;
            #pragma unroll
            for (int half = 0; half < 2; half++) {
                int r = rr + half * 8;
                float* orow = Wout + ((size_t)bh * Sn + r) * Sn;
                orow[cc]     = acc[i][j][half * 2 + 0] * scale + mask[bb * Sn + cc];
                orow[cc + 1] = acc[i][j][half * 2 + 1] * scale + mask[bb * Sn + cc + 1];
            }
        }
    }
}

// ---------------------------------------------------------------------------
// Kernel 3: row softmax over the causal band only (tail pre-zeroed by qkv).
// ---------------------------------------------------------------------------
__global__ __launch_bounds__(256) void softmax_kernel(float* __restrict__ Wm) {
    __shared__ float buf[Sn];
    __shared__ float red[8];
    int row = blockIdx.x;
    int q = row & (Sn - 1);
    int len = q + 1;
    int blockend = ((q >> 7) + 1) << 7;
    float* wrow = Wm + (size_t)row * Sn;
    size_t wb = (size_t)row * Sn;
    int tid = threadIdx.x;
    int lane = tid & 31, warp = tid >> 5;

    float mx = -1e30f;
    for (int c = tid * 4; c < blockend; c += 1024) {
        float4 v = *(const float4*)&wrow[c];
        *(float4*)&buf[c] = v;
        if (c + 3 < len) {
            mx = fmaxf(mx, fmaxf(fmaxf(v.x, v.y), fmaxf(v.z, v.w)));
        } else {
            if (c     < len) mx = fmaxf(mx, v.x);
            if (c + 1 < len) mx = fmaxf(mx, v.y);
            if (c + 2 < len) mx = fmaxf(mx, v.z);
            if (c + 3 < len) mx = fmaxf(mx, v.w);
        }
    }
    #pragma unroll
    for (int o = 16; o > 0; o >>= 1) mx = fmaxf(mx, __shfl_xor_sync(0xffffffffu, mx, o));
    if (lane == 0) red[warp] = mx;
    __syncthreads();
    if (tid < 32) {
        float t = (tid < 8) ? red[tid] : -1e30f;
        #pragma unroll
        for (int o = 4; o > 0; o >>= 1) t = fmaxf(t, __shfl_xor_sync(0xffffffffu, t, o));
        if (tid == 0) red[0] = t;
    }
    __syncthreads();
    mx = red[0];
    __syncthreads();

    float sum = 0.0f;
    for (int c = tid * 4; c < blockend; c += 1024) {
        float4 v = *(const float4*)&buf[c];
        float e0 = (c     < len) ? __expf(v.x - mx) : 0.0f;
        float e1 = (c + 1 < len) ? __expf(v.y - mx) : 0.0f;
        float e2 = (c + 2 < len) ? __expf(v.z - mx) : 0.0f;
        float e3 = (c + 3 < len) ? __expf(v.w - mx) : 0.0f;
        sum += (e0 + e1) + (e2 + e3);
        *(float4*)&buf[c] = make_float4(e0, e1, e2, e3);
    }
    #pragma unroll
    for (int o = 16; o > 0; o >>= 1) sum += __shfl_xor_sync(0xffffffffu, sum, o);
    if (lane == 0) red[warp] = sum;
    __syncthreads();
    if (tid < 32) {
        float t = (tid < 8) ? red[tid] : 0.0f;
        #pragma unroll
        for (int o = 4; o > 0; o >>= 1) t += __shfl_xor_sync(0xffffffffu, t, o);
        if (tid == 0) red[0] = t;
    }
    __syncthreads();
    float inv = 1.0f / red[0];

    for (int c = tid * 4; c < blockend; c += 1024) {
        float4 v = *(const float4*)&buf[c];
        v.x *= inv; v.y *= inv; v.z *= inv; v.w *= inv;
        *(float4*)&wrow[c] = v;
        *(uint2*)&g_w_h[wb + c] = make_uint2(pack2(v.x, v.y), pack2(v.z, v.w));
    }
}

// ---------------------------------------------------------------------------
// Kernel 4: attn_heads = weights @ V (unchanged from R13).
// ---------------------------------------------------------------------------
__global__ __launch_bounds__(256, 3) void av_kernel() {
    extern __shared__ __align__(16) char dynsmem[];
    const uint32_t smb = s2u(dynsmem);
    int qb = gridDim.x - 1 - blockIdx.x;
    int bh = blockIdx.y;
    int tid = threadIdx.x, lane = tid & 31, wid = tid >> 5;
    int row0 = qb * 128;
    int mbase = (wid & 3) * 32, nbase = (wid >> 2) * 32;
    int srow = tid >> 1, sh = tid & 1;
    int brow = tid >> 2, bq = tid & 3;
    const __half* gA = g_w_h + (size_t)bh * Sn * Sn + (size_t)(row0 + srow) * Sn + sh * 32;
    const __half* gB = g_v_h + ((size_t)bh * HDn + brow) * Sn + bq * 16;
    uint32_t dA[4];
    #pragma unroll
    for (int i = 0; i < 4; i++) dA[i] = swz(srow, sh * 4 + i);
    uint32_t dB0 = 16384u + swz(brow, bq * 2), dB1 = 16384u + swz(brow, bq * 2 + 1);

    float acc[2][4][4] = {};
    const int T = (qb + 1) * 2;

    #define AISSUE(t) do { uint32_t sb = smb + ((t) & 1) * SLOT_AV; \
        _Pragma("unroll") for (int i = 0; i < 4; i++) \
            cpa16(sb + dA[i], gA + (t) * 64 + i * 8); \
        cpa16(sb + dB0, gB + (t) * 64);  cpa16(sb + dB1, gB + (t) * 64 + 8); } while (0)

    AISSUE(0); CP_COMMIT();
    for (int t = 0; t < T; t++) {
        CP_WAIT0();
        __syncthreads();
        if (t + 1 < T) AISSUE(t + 1);
        CP_COMMIT();
        cstage_av(smb + (t & 1) * SLOT_AV, acc, mbase, nbase, lane);
    }
    #undef AISSUE

    #pragma unroll
    for (int i = 0; i < 2; i++) {
        #pragma unroll
        for (int j = 0; j < 4; j++) {
            int rr = row0 + mbase + i * 16 + (lane >> 2);
            int cc = nbase + j * 8 + (lane & 3) * 2;
            #pragma unroll
            for (int half = 0; half < 2; half++) {
                int r = rr + half * 8;
                size_t idx = ((size_t)bh * Sn + r) * HDn + cc;
                *(uint32_t*)&g_att_h[idx] =
                    pack2(acc[i][j][half * 2 + 0], acc[i][j][half * 2 + 1]);
            }
        }
    }
}

// ---------------------------------------------------------------------------
// Kernel 5: output projection (unchanged from R13).
// ---------------------------------------------------------------------------
__global__ __launch_bounds__(256, 2) void proj_gemm(const float* __restrict__ bias,
                                                    float* __restrict__ out) {
    extern __shared__ __align__(16) char dynsmem[];
    const uint32_t smb = s2u(dynsmem);
    const int K = 1024, N = 1024;
    int tid = threadIdx.x, lane = tid & 31, wid = tid >> 5;
    int row0 = blockIdx.y * 128, col0 = blockIdx.x * 128;
    int mbase = (wid & 1) * 64, nbase = (wid >> 1) * 32;
    int srow = tid >> 1, sh = tid & 1;
    int arow = row0 + srow;
    int ab = arow >> 11, as = arow & 2047;
    size_t abase = (((size_t)ab * Hn) * Sn + as) * HDn + sh * 32;
    const __half* gB = s_wp_h + (size_t)(col0 + srow) * K + sh * 32;
    uint32_t dA[4];
    #pragma unroll
    for (int i = 0; i < 4; i++) dA[i] = swz(srow, sh * 4 + i);

    float acc[4][4][4] = {};
    const int T = K / 64;

    #define PISSUE(t) do { uint32_t sb = smb + ((t) & 1) * SLOT_SS; \
        size_t so = abase + (size_t)(t) * Sn * HDn; \
        _Pragma("unroll") for (int i = 0; i < 4; i++) { \
            cpa16(sb + dA[i],          g_att_h + so + i * 8); \
            cpa16(sb + 16384 + dA[i],  gB + (t) * 64 + i * 8); } } while (0)

    PISSUE(0); CP_COMMIT();
    for (int t = 0; t < T; t++) {
        CP_WAIT0();
        __syncthreads();
        if (t + 1 < T) PISSUE(t + 1);
        CP_COMMIT();
        cstage_ss(smb + (t & 1) * SLOT_SS, acc, mbase, nbase, lane);
    }
    #undef PISSUE

    #pragma unroll
    for (int i = 0; i < 4; i++) {
        #pragma unroll
        for (int j = 0; j < 4; j++) {
            int rr = row0 + mbase + i * 16 + (lane >> 2);
            int cc = col0 + nbase + j * 8 + (lane & 3) * 2;
            #pragma unroll
            for (int half = 0; half < 2; half++) {
                int r = rr + half * 8;
                out[(size_t)r * N + cc]     = acc[i][j][half * 2 + 0] + bias[cc];
                out[(size_t)r * N + cc + 1] = acc[i][j][half * 2 + 1] + bias[cc + 1];
            }
        }
    }
}

// ---------------------------------------------------------------------------
extern "C" void kernel_launch(void* const* d_in, const int* in_sizes, int n_in,
                              void* d_out, int out_size) {
    (void)in_sizes; (void)n_in; (void)out_size;
    const float* hs     = (const float*)d_in[0];
    const float* mask   = (const float*)d_in[1];
    const float* w_attn = (const float*)d_in[2];
    const float* b_attn = (const float*)d_in[3];
    const float* w_proj = (const float*)d_in[4];
    const float* b_proj = (const float*)d_in[5];

    float* attn_out = (float*)d_out;                          // [B,S,D]
    float* weights  = (float*)d_out + (size_t)Bn * Sn * Dn;   // [B,H,S,S]

    cudaFuncSetAttribute(qkv_gemm,      cudaFuncAttributeMaxDynamicSharedMemorySize, SMEM_SS);
    cudaFuncSetAttribute(scores_kernel, cudaFuncAttributeMaxDynamicSharedMemorySize, SMEM_SC);
    cudaFuncSetAttribute(av_kernel,     cudaFuncAttributeMaxDynamicSharedMemorySize, SMEM_AV);
    cudaFuncSetAttribute(proj_gemm,     cudaFuncAttributeMaxDynamicSharedMemorySize, SMEM_SS);

    __half *wa_h, *wp_h;
    cudaGetSymbolAddress((void**)&wa_h, s_wa_h);
    cudaGetSymbolAddress((void**)&wp_h, s_wp_h);

    split_hs<<<BSn * Dn / 1024, 256>>>(hs);
    split_transpose<<<dim3(N3D / 32, Dn / 32), 256>>>(w_attn, wa_h, Dn, N3D);
    split_transpose<<<dim3(Dn / 32, Dn / 32), 256>>>(w_proj, wp_h, Dn, Dn);
    qkv_gemm<<<dim3(N3D / 128, BSn / 128), 256, SMEM_SS>>>(b_attn, weights);
    scores_kernel<<<dim3(136, Bn * Hn), 256, SMEM_SC>>>(mask, weights);
    softmax_kernel<<<dim3(Bn * Hn * Sn), 256>>>(weights);
    av_kernel<<<dim3(Sn / 128, Bn * Hn), 256, SMEM_AV>>>();
    proj_gemm<<<dim3(Dn / 128, BSn / 128), 256, SMEM_SS>>>(b_proj, attn_out);
}